// round 1
// baseline (speedup 1.0000x reference)
#include <cuda_runtime.h>

#define DD 64
#define NMAX 100000

// Scratch: [0],[1] = ping-pong propagation buffers; [2..4] = per-graph results.
__device__ float g_mem[5][(size_t)NMAX * DD];
__device__ float g_dinv[NMAX];
__device__ int   g_deg[NMAX];
__device__ float g_wa[DD];

__global__ void zero_deg_kernel(int N) {
    int i = blockIdx.x * blockDim.x + threadIdx.x;
    if (i < N) g_deg[i] = 0;
}

__global__ void count_deg_kernel(const int* __restrict__ dst, int E) {
    int e = blockIdx.x * blockDim.x + threadIdx.x;
    if (e < E) atomicAdd(&g_deg[dst[e]], 1);
}

__global__ void dinv_kernel(int N) {
    int i = blockIdx.x * blockDim.x + threadIdx.x;
    if (i < N) {
        int d = g_deg[i];
        g_dinv[i] = (d > 0) ? rsqrtf((float)d) : 0.0f;
    }
}

// h0 = emb_table[x]  (16 lanes per row, float4 each)
__global__ void gather_h0_kernel(const float* __restrict__ emb, const int* __restrict__ x, int N) {
    int t = blockIdx.x * blockDim.x + threadIdx.x;
    int row = t >> 4, lane = t & 15;
    if (row >= N) return;
    int xr = x[row];
    float4 v = reinterpret_cast<const float4*>(emb + (size_t)xr * DD)[lane];
    reinterpret_cast<float4*>(&g_mem[0][(size_t)row * DD])[lane] = v;
}

__global__ void zero_buf_kernel(int id, int n4) {
    int t = blockIdx.x * blockDim.x + threadIdx.x;
    if (t < n4) reinterpret_cast<float4*>(g_mem[id])[t] = make_float4(0.f, 0.f, 0.f, 0.f);
}

// One propagation layer: hn[dst] += h[src] * dinv[src]*dinv[dst].
// 16 lanes per edge; float4 load + red.global.add.v4.f32 store (4x fewer atomics).
__global__ void scatter_kernel(int hin, int hout,
                               const int* __restrict__ src, const int* __restrict__ dst,
                               int E) {
    int t = blockIdx.x * blockDim.x + threadIdx.x;
    int e = t >> 4, lane = t & 15;
    if (e >= E) return;
    int s = src[e], d = dst[e];
    float norm = g_dinv[s] * g_dinv[d];
    float4 v = reinterpret_cast<const float4*>(g_mem[hin] + (size_t)s * DD)[lane];
    v.x *= norm; v.y *= norm; v.z *= norm; v.w *= norm;
    float* addr = g_mem[hout] + (size_t)d * DD + lane * 4;
    asm volatile("red.global.add.v4.f32 [%0], {%1, %2, %3, %4};"
                 :: "l"(addr), "f"(v.x), "f"(v.y), "f"(v.z), "f"(v.w)
                 : "memory");
}

// wa[k] = sum_j W[k][j] * a[j]   (score = emb . wa)
__global__ void wa_kernel(const float* __restrict__ W, const float* __restrict__ a) {
    int k = threadIdx.x;
    float s = 0.f;
    #pragma unroll
    for (int j = 0; j < DD; j++) s += W[k * DD + j] * a[j];
    g_wa[k] = s;
}

__device__ __forceinline__ float warp_sum(float p) {
    #pragma unroll
    for (int o = 16; o > 0; o >>= 1) p += __shfl_xor_sync(0xFFFFFFFFu, p, o);
    return p;
}

// One warp per (user,item) pair: per-node channel softmax + combine + dot.
__global__ void final_kernel(const int* __restrict__ user, const int* __restrict__ item,
                             float* __restrict__ out, int B) {
    int w = (blockIdx.x * blockDim.x + threadIdx.x) >> 5;
    int lane = threadIdx.x & 31;
    if (w >= B) return;
    int u = user[w], it = item[w];

    float eu[3][2], ev[3][2];
    #pragma unroll
    for (int g = 0; g < 3; g++) {
        const float* base = g_mem[2 + g];
        eu[g][0] = base[(size_t)u * DD + lane];
        eu[g][1] = base[(size_t)u * DD + lane + 32];
        ev[g][0] = base[(size_t)it * DD + lane];
        ev[g][1] = base[(size_t)it * DD + lane + 32];
    }
    float wa0 = g_wa[lane], wa1 = g_wa[lane + 32];

    float su[3], sv[3];
    #pragma unroll
    for (int g = 0; g < 3; g++) {
        su[g] = warp_sum(eu[g][0] * wa0 + eu[g][1] * wa1);
        sv[g] = warp_sum(ev[g][0] * wa0 + ev[g][1] * wa1);
    }

    // softmax over the 3 channels (user node)
    float mu = fmaxf(su[0], fmaxf(su[1], su[2]));
    float a0 = __expf(su[0] - mu), a1 = __expf(su[1] - mu), a2 = __expf(su[2] - mu);
    float ainv = 1.0f / (a0 + a1 + a2);
    float wu0 = a0 * ainv, wu1 = a1 * ainv, wu2 = a2 * ainv;
    // (item node)
    float mv = fmaxf(sv[0], fmaxf(sv[1], sv[2]));
    float b0 = __expf(sv[0] - mv), b1 = __expf(sv[1] - mv), b2 = __expf(sv[2] - mv);
    float binv = 1.0f / (b0 + b1 + b2);
    float wv0 = b0 * binv, wv1 = b1 * binv, wv2 = b2 * binv;

    float nu0 = wu0 * eu[0][0] + wu1 * eu[1][0] + wu2 * eu[2][0];
    float nu1 = wu0 * eu[0][1] + wu1 * eu[1][1] + wu2 * eu[2][1];
    float ni0 = wv0 * ev[0][0] + wv1 * ev[1][0] + wv2 * ev[2][0];
    float ni1 = wv0 * ev[0][1] + wv1 * ev[1][1] + wv2 * ev[2][1];

    float dot = warp_sum(nu0 * ni0 + nu1 * ni1);
    if (lane == 0) out[w] = dot;
}

extern "C" void kernel_launch(void* const* d_in, const int* in_sizes, int n_in,
                              void* d_out, int out_size) {
    const int*   user = (const int*)d_in[0];
    const int*   item = (const int*)d_in[1];
    const int*   x    = (const int*)d_in[2];
    const int*   ei[3] = { (const int*)d_in[3], (const int*)d_in[4], (const int*)d_in[5] };
    const float* emb  = (const float*)d_in[6];
    const float* W    = (const float*)d_in[7];
    const float* a    = (const float*)d_in[8];
    float* out = (float*)d_out;

    int B = in_sizes[0];
    int N = in_sizes[2];
    int E = in_sizes[3] / 2;
    if (N > NMAX) return;

    const int T = 256;
    int n4     = N * DD / 4;
    int nb_N   = (N + T - 1) / T;
    int nb_E   = (E + T - 1) / T;
    int nb_n4  = (n4 + T - 1) / T;
    int nb_N16 = (int)(((long long)N * 16 + T - 1) / T);
    int nb_E16 = (int)(((long long)E * 16 + T - 1) / T);

    for (int g = 0; g < 3; g++) {
        const int* src  = ei[g];
        const int* dstp = ei[g] + E;

        // degree / dinv (layer-invariant per graph)
        zero_deg_kernel<<<nb_N, T>>>(N);
        count_deg_kernel<<<nb_E, T>>>(dstp, E);
        dinv_kernel<<<nb_N, T>>>(N);

        // h0 = emb_table[x]
        gather_h0_kernel<<<nb_N16, T>>>(emb, x, N);

        // layer 1: buf0 -> buf1
        zero_buf_kernel<<<nb_n4, T>>>(1, n4);
        scatter_kernel<<<nb_E16, T>>>(0, 1, src, dstp, E);
        // layer 2: buf1 -> buf0
        zero_buf_kernel<<<nb_n4, T>>>(0, n4);
        scatter_kernel<<<nb_E16, T>>>(1, 0, src, dstp, E);
        // layer 3: buf0 -> result[g]
        zero_buf_kernel<<<nb_n4, T>>>(2 + g, n4);
        scatter_kernel<<<nb_E16, T>>>(0, 2 + g, src, dstp, E);
    }

    wa_kernel<<<1, DD>>>(W, a);
    final_kernel<<<(B * 32 + T - 1) / T, T>>>(user, item, out, B);
}